// round 10
// baseline (speedup 1.0000x reference)
#include <cuda_runtime.h>
#include <cuda_fp16.h>

#define NN 100000
#define EE 3200000
#define GG 100
#define ST48 32   // padded row stride in half2 (64 halves = 128B) for F=48 layers
#define ST16 8    // row stride in half2 (32B) for F=16 layer

// ---------------- device scratch ----------------
__device__ int   g_pre[2 * NN];       // [0:NN) out-degree, [NN:2NN) in-degree / cnt
__device__ float g_dis[NN];
__device__ float g_diag[NN];
__device__ int   g_rowptr[NN + 1];
__device__ int2  g_edge[EE];          // {src, weight as half2 (broadcast) bits}, grouped by dst
__device__ __half g_x16[NN * 16];
__device__ __half g_T1[NN * 64];
__device__ __half g_T2[NN * 64];
__device__ __half g_T3[NN * 64];
__device__ __half g_T4[NN * 64];
__device__ __half g_hA[NN * 64];
__device__ __half g_hB[NN * 64];

// ---------------- graph preprocessing ----------------
__global__ void k_degree(const int* __restrict__ src, const int* __restrict__ dst) {
    int e = blockIdx.x * blockDim.x + threadIdx.x;
    if (e >= EE) return;
    atomicAdd(&g_pre[src[e]], 1);
    atomicAdd(&g_pre[NN + dst[e]], 1);
}

// single block: per-node terms + exclusive scan of in-degree -> rowptr; re-zero cnt.
__global__ void k_scan(const int* __restrict__ batch, const float* __restrict__ lmax) {
    __shared__ int sums[1024];
    const int tid = threadIdx.x;
    const int CH = (NN + 1023) / 1024;
    int start = tid * CH;
    int end = start + CH; if (end > NN) end = NN; if (start > NN) start = NN;
    int s = 0;
    for (int i = start; i < end; i++) {
        s += g_pre[NN + i];
        float d = (float)g_pre[i];
        g_dis[i] = (d > 0.0f) ? rsqrtf(d) : 0.0f;
        g_diag[i] = 2.0f / lmax[batch[i]] - 1.0f;
    }
    sums[tid] = s;
    __syncthreads();
    for (int off = 1; off < 1024; off <<= 1) {
        int v = (tid >= off) ? sums[tid - off] : 0;
        __syncthreads();
        sums[tid] += v;
        __syncthreads();
    }
    int run = sums[tid] - s;
    for (int i = start; i < end; i++) {
        g_rowptr[i] = run;
        run += g_pre[NN + i];
        g_pre[NN + i] = 0;
    }
    if (tid == 1023) g_rowptr[NN] = run;
}

// fill CSR edges; low threads also convert x -> fp16
__global__ void k_fill(const int* __restrict__ src, const int* __restrict__ dst,
                       const float* __restrict__ lmax, const float* __restrict__ x) {
    int e = blockIdx.x * blockDim.x + threadIdx.x;
    if (e < NN * 8) {
        float2 v = reinterpret_cast<const float2*>(x)[e];
        reinterpret_cast<__half2*>(g_x16)[e] = __floats2half2_rn(v.x, v.y);
    }
    if (e >= EE) return;
    int s = src[e], d = dst[e];
    int pos = g_rowptr[d] + atomicAdd(&g_pre[NN + d], 1);
    float w = -2.0f * g_dis[s] * g_dis[d] / lmax[s / (NN / GG)];
    __half2 w2 = __half2half2(__float2half_rn(w));
    g_edge[pos] = make_int2(s, *reinterpret_cast<const int*>(&w2));
}

// ---------------- Chebyshev propagation (fp16, half2 FMA, broadcast edge loads) ------
// F = 16: 8 lanes per node (4 nodes/warp), each lane owns one half2 column pair.
template <bool HASPREV>
__global__ void k_prop16(const __half2* __restrict__ tin, const __half2* __restrict__ tprev,
                         __half2* __restrict__ tout, float alpha) {
    int t = blockIdx.x * blockDim.x + threadIdx.x;
    int n = t >> 3;
    if (n >= NN) return;
    int lane = t & 7;
    int beg = g_rowptr[n], end = g_rowptr[n + 1];
    __half2 acc = __float2half2_rn(0.0f);
    int e = beg;
    for (; e + 8 <= end; e += 8) {
        int2 E[8];
#pragma unroll
        for (int j = 0; j < 8; j++) E[j] = g_edge[e + j];
        __half2 f[8];
#pragma unroll
        for (int j = 0; j < 8; j++) f[j] = tin[E[j].x * ST16 + lane];
#pragma unroll
        for (int j = 0; j < 8; j++)
            acc = __hfma2(*reinterpret_cast<const __half2*>(&E[j].y), f[j], acc);
    }
    for (; e < end; e++) {
        int2 E0 = g_edge[e];
        __half2 f0 = tin[E0.x * ST16 + lane];
        acc = __hfma2(*reinterpret_cast<const __half2*>(&E0.y), f0, acc);
    }
    float2 a = __half22float2(acc);
    float dg = g_diag[n];
    float2 fs = __half22float2(tin[n * ST16 + lane]);
    float rx = alpha * (dg * fs.x + a.x);
    float ry = alpha * (dg * fs.y + a.y);
    if (HASPREV) {
        float2 fp = __half22float2(tprev[n * ST16 + lane]);
        rx -= fp.x; ry -= fp.y;
    }
    tout[n * ST16 + lane] = __floats2half2_rn(rx, ry);
}

// F = 48: warp per node, padded 128B rows (1 wavefront per gather), lanes 0..23 active.
template <bool HASPREV>
__global__ void k_prop48(const __half2* __restrict__ tin, const __half2* __restrict__ tprev,
                         __half2* __restrict__ tout, float alpha) {
    int n = (blockIdx.x * blockDim.x + threadIdx.x) >> 5;
    if (n >= NN) return;
    int lane = threadIdx.x & 31;
    bool act = lane < 24;
    int li = act ? lane : 0;
    int beg = g_rowptr[n], end = g_rowptr[n + 1];
    __half2 acc = __float2half2_rn(0.0f);
    int e = beg;
    for (; e + 8 <= end; e += 8) {
        int2 E[8];
#pragma unroll
        for (int j = 0; j < 8; j++) E[j] = g_edge[e + j];
        __half2 f[8];
#pragma unroll
        for (int j = 0; j < 8; j++) f[j] = tin[E[j].x * ST48 + li];
#pragma unroll
        for (int j = 0; j < 8; j++)
            acc = __hfma2(*reinterpret_cast<const __half2*>(&E[j].y), f[j], acc);
    }
    for (; e < end; e++) {
        int2 E0 = g_edge[e];
        __half2 f0 = tin[E0.x * ST48 + li];
        acc = __hfma2(*reinterpret_cast<const __half2*>(&E0.y), f0, acc);
    }
    if (act) {
        float2 a = __half22float2(acc);
        float dg = g_diag[n];
        float2 fs = __half22float2(tin[n * ST48 + lane]);
        float rx = alpha * (dg * fs.x + a.x);
        float ry = alpha * (dg * fs.y + a.y);
        if (HASPREV) {
            float2 fp = __half22float2(tprev[n * ST48 + lane]);
            rx -= fp.x; ry -= fp.y;
        }
        tout[n * ST48 + lane] = __floats2half2_rn(rx, ry);
    }
}

// ---------------- fused layer output: h = relu(b + sum_k T_k @ W[k]) ----------------
// TS = input row stride (half2). Output rows padded to ST48.
template <int FIN, int TS>
__global__ void k_mix(const __half2* __restrict__ T0, const __half2* __restrict__ T1,
                      const __half2* __restrict__ T2, const __half2* __restrict__ T3,
                      const __half2* __restrict__ T4,
                      const float* __restrict__ W, const float* __restrict__ b,
                      __half2* __restrict__ hout) {
    __shared__ __align__(16) float sW[5 * FIN * 48];
    const int tot = 5 * FIN * 48;
    for (int i = threadIdx.x; i < tot; i += blockDim.x) sW[i] = W[i];
    __syncthreads();
    int gid = blockIdx.x * blockDim.x + threadIdx.x;
    int n = gid / 12;
    int f = (gid % 12) * 4;
    if (n >= NN) return;
    const __half2* Ts[5] = {T0, T1, T2, T3, T4};
    float4 acc = *reinterpret_cast<const float4*>(&b[f]);
#pragma unroll
    for (int k = 0; k < 5; k++) {
        const __half2* T = Ts[k] + n * TS;
        const float* wk = &sW[k * FIN * 48 + f];
#pragma unroll
        for (int i2 = 0; i2 < FIN / 2; i2++) {
            float2 v = __half22float2(T[i2]);
            float4 w0 = *reinterpret_cast<const float4*>(wk + (2 * i2) * 48);
            float4 w1 = *reinterpret_cast<const float4*>(wk + (2 * i2 + 1) * 48);
            acc.x += v.x * w0.x + v.y * w1.x;
            acc.y += v.x * w0.y + v.y * w1.y;
            acc.z += v.x * w0.z + v.y * w1.z;
            acc.w += v.x * w0.w + v.y * w1.w;
        }
    }
    acc.x = fmaxf(acc.x, 0.0f);
    acc.y = fmaxf(acc.y, 0.0f);
    acc.z = fmaxf(acc.z, 0.0f);
    acc.w = fmaxf(acc.w, 0.0f);
    hout[n * ST48 + f / 2]     = __floats2half2_rn(acc.x, acc.y);
    hout[n * ST48 + f / 2 + 1] = __floats2half2_rn(acc.z, acc.w);
}

// ---------------- global_add_pool + MLP head (padded rows: 64 halves) ----------------
__global__ void k_pool(const __half* __restrict__ h,
                       const float* __restrict__ fc1w, const float* __restrict__ fc1b,
                       const float* __restrict__ fc2w, const float* __restrict__ fc2b,
                       float* __restrict__ out) {
    const int g = blockIdx.x;
    const int tid = threadIdx.x;
    const int r = tid / 48, f = tid % 48;
    const int base = g * (NN / GG);
    float a = 0.0f;
    for (int n = base + r; n < base + (NN / GG); n += 10) a += __half2float(h[n * 64 + f]);
    __shared__ float red[480];
    __shared__ float pooled[48];
    __shared__ float o1[32];
    red[tid] = a;
    __syncthreads();
    if (tid < 48) {
        float s = 0.0f;
        for (int rr = 0; rr < 10; rr++) s += red[rr * 48 + tid];
        pooled[tid] = s;
    }
    __syncthreads();
    if (tid < 32) {
        float s = fc1b[tid];
        for (int i = 0; i < 48; i++) s += pooled[i] * fc1w[i * 32 + tid];
        o1[tid] = fmaxf(s, 0.0f);
    }
    __syncthreads();
    if (tid == 0) {
        float s = fc2b[0];
        for (int j = 0; j < 32; j++) s += o1[j] * fc2w[j];
        out[g] = s;
    }
}

// ---------------- host launcher ----------------
extern "C" void kernel_launch(void* const* d_in, const int* in_sizes, int n_in,
                              void* d_out, int out_size) {
    const float* x     = (const float*)d_in[0];
    const int*   ei    = (const int*)d_in[1];
    const int*   src   = ei;
    const int*   dst   = ei + EE;
    const int*   batch = (const int*)d_in[2];
    const float* lmax  = (const float*)d_in[3];
    const float* W[5]  = {(const float*)d_in[4], (const float*)d_in[6], (const float*)d_in[8],
                          (const float*)d_in[10], (const float*)d_in[12]};
    const float* B[5]  = {(const float*)d_in[5], (const float*)d_in[7], (const float*)d_in[9],
                          (const float*)d_in[11], (const float*)d_in[13]};
    const float* fc1w = (const float*)d_in[14];
    const float* fc1b = (const float*)d_in[15];
    const float* fc2w = (const float*)d_in[16];
    const float* fc2b = (const float*)d_in[17];
    float* out = (float*)d_out;

    void* p;
    cudaGetSymbolAddress(&p, g_pre);  int* pre = (int*)p;
    cudaGetSymbolAddress(&p, g_x16);  __half2* x16 = (__half2*)p;
    cudaGetSymbolAddress(&p, g_T1);   __half2* T1 = (__half2*)p;
    cudaGetSymbolAddress(&p, g_T2);   __half2* T2 = (__half2*)p;
    cudaGetSymbolAddress(&p, g_T3);   __half2* T3 = (__half2*)p;
    cudaGetSymbolAddress(&p, g_T4);   __half2* T4 = (__half2*)p;
    cudaGetSymbolAddress(&p, g_hA);   __half2* hA = (__half2*)p;
    cudaGetSymbolAddress(&p, g_hB);   __half2* hB = (__half2*)p;

    cudaMemsetAsync(pre, 0, 2 * NN * sizeof(int), 0);
    k_degree<<<(EE + 255) / 256, 256>>>(src, dst);
    k_scan<<<1, 1024>>>(batch, lmax);
    k_fill<<<(EE + 255) / 256, 256>>>(src, dst, lmax, x);

    const int PB = 256;
    const int pgrid48 = (NN * 32 + PB - 1) / PB;  // warp per node
    const int pgrid16 = (NN * 8 + PB - 1) / PB;   // 8 lanes per node
    const int mgrid = (NN * 12 + 255) / 256;

    // layer 1 (F_in = 16, T0 = x16)
    k_prop16<false><<<pgrid16, PB>>>(x16, nullptr, T1, 1.0f);
    k_prop16<true><<<pgrid16, PB>>>(T1, x16, T2, 2.0f);
    k_prop16<true><<<pgrid16, PB>>>(T2, T1, T3, 2.0f);
    k_prop16<true><<<pgrid16, PB>>>(T3, T2, T4, 2.0f);
    k_mix<16, ST16><<<mgrid, 256>>>(x16, T1, T2, T3, T4, W[0], B[0], hA);

    // layers 2..5 (F_in = 48), ping-pong hA <-> hB
    __half2* cur = hA;
    __half2* nxt = hB;
    for (int l = 1; l < 5; l++) {
        k_prop48<false><<<pgrid48, PB>>>(cur, nullptr, T1, 1.0f);
        k_prop48<true><<<pgrid48, PB>>>(T1, cur, T2, 2.0f);
        k_prop48<true><<<pgrid48, PB>>>(T2, T1, T3, 2.0f);
        k_prop48<true><<<pgrid48, PB>>>(T3, T2, T4, 2.0f);
        k_mix<48, ST48><<<mgrid, 256>>>(cur, T1, T2, T3, T4, W[l], B[l], nxt);
        __half2* t = cur; cur = nxt; nxt = t;
    }

    k_pool<<<GG, 480>>>((const __half*)cur, fc1w, fc1b, fc2w, fc2b, out);
}

// round 11
// speedup vs baseline: 1.2466x; 1.2466x over previous
#include <cuda_runtime.h>
#include <cuda_fp16.h>

#define NN 100000
#define EE 3200000
#define GG 100
#define HH 48

// ---------------- device scratch ----------------
__device__ int   g_degi[NN];
__device__ float g_dis[NN];
__device__ float g_diag[NN];
__device__ int   g_cnt[NN];
__device__ int   g_rowptr[NN + 1];
__device__ int4  g_edge4[EE / 2];     // pairs of {src, weight-as-half2-broadcast bits}
__device__ __half g_x16[NN * 16];
__device__ __half g_T1[NN * HH];
__device__ __half g_T2[NN * HH];
__device__ __half g_T3[NN * HH];
__device__ __half g_T4[NN * HH];
__device__ __half g_hA[NN * HH];
__device__ __half g_hB[NN * HH];

__device__ __forceinline__ __half2 b2h2(int v) {
    union { int i; __half2 h; } u; u.i = v; return u.h;
}

// ---------------- graph preprocessing (R5 structure: parallel kernels) ----------------
__global__ void k_degree(const int* __restrict__ src, const int* __restrict__ dst) {
    int e = blockIdx.x * blockDim.x + threadIdx.x;
    if (e >= EE) return;
    atomicAdd(&g_degi[src[e]], 1);
    atomicAdd(&g_cnt[dst[e]], 1);
}

__global__ void k_node(const int* __restrict__ batch, const float* __restrict__ lmax) {
    int n = blockIdx.x * blockDim.x + threadIdx.x;
    if (n >= NN) return;
    float d = (float)g_degi[n];
    g_dis[n] = (d > 0.0f) ? rsqrtf(d) : 0.0f;
    g_diag[n] = 2.0f / lmax[batch[n]] - 1.0f;
}

// single-block exclusive scan of g_cnt -> g_rowptr
__global__ void k_scan() {
    __shared__ int sums[1024];
    const int tid = threadIdx.x;
    const int CH = (NN + 1023) / 1024;
    int start = tid * CH;
    int end = start + CH; if (end > NN) end = NN; if (start > NN) start = NN;
    int s = 0;
    for (int i = start; i < end; i++) s += g_cnt[i];
    sums[tid] = s;
    __syncthreads();
    for (int off = 1; off < 1024; off <<= 1) {
        int v = (tid >= off) ? sums[tid - off] : 0;
        __syncthreads();
        sums[tid] += v;
        __syncthreads();
    }
    int run = sums[tid] - s;
    for (int i = start; i < end; i++) {
        g_rowptr[i] = run;
        run += g_cnt[i];
    }
    if (tid == 1023) g_rowptr[NN] = run;
}

__global__ void k_fill(const int* __restrict__ src, const int* __restrict__ dst,
                       const float* __restrict__ lmax) {
    int e = blockIdx.x * blockDim.x + threadIdx.x;
    if (e >= EE) return;
    int s = src[e], d = dst[e];
    int pos = g_rowptr[d] + atomicAdd(&g_cnt[d], 1);
    float w = -2.0f * g_dis[s] * g_dis[d] / lmax[s / (NN / GG)];
    __half2 w2 = __half2half2(__float2half_rn(w));
    reinterpret_cast<int2*>(g_edge4)[pos] = make_int2(s, *reinterpret_cast<const int*>(&w2));
}

__global__ void k_xcast(const float* __restrict__ x) {
    int i = blockIdx.x * blockDim.x + threadIdx.x;
    if (i >= NN * 8) return;
    float2 v = reinterpret_cast<const float2*>(x)[i];
    reinterpret_cast<__half2*>(g_x16)[i] = __floats2half2_rn(v.x, v.y);
}

// ---------------- Chebyshev propagation (fp16, HFMA2, paired LDG.128 edge loads) -----
// F = 16: 8 lanes per node (4 nodes/warp), each lane owns one half2 column pair.
template <bool HASPREV>
__global__ void k_prop16(const __half2* __restrict__ tin, const __half2* __restrict__ tprev,
                         __half2* __restrict__ tout, float alpha) {
    int t = blockIdx.x * blockDim.x + threadIdx.x;
    int n = t >> 3;
    if (n >= NN) return;
    int lane = t & 7;
    int beg = g_rowptr[n], end = g_rowptr[n + 1];
    const int2* e2 = reinterpret_cast<const int2*>(g_edge4);
    __half2 acc = __float2half2_rn(0.0f);
    int e = beg;
    if ((e & 1) && e < end) {                      // align to int4 boundary
        int2 E0 = e2[e];
        acc = __hfma2(b2h2(E0.y), tin[E0.x * 8 + lane], acc);
        e++;
    }
    for (; e + 8 <= end; e += 8) {
        int4 P[4];
#pragma unroll
        for (int j = 0; j < 4; j++) P[j] = g_edge4[(e >> 1) + j];
        __half2 f[8];
#pragma unroll
        for (int j = 0; j < 4; j++) {
            f[2 * j]     = tin[P[j].x * 8 + lane];
            f[2 * j + 1] = tin[P[j].z * 8 + lane];
        }
#pragma unroll
        for (int j = 0; j < 4; j++) {
            acc = __hfma2(b2h2(P[j].y), f[2 * j], acc);
            acc = __hfma2(b2h2(P[j].w), f[2 * j + 1], acc);
        }
    }
    for (; e + 2 <= end; e += 2) {
        int4 P = g_edge4[e >> 1];
        acc = __hfma2(b2h2(P.y), tin[P.x * 8 + lane], acc);
        acc = __hfma2(b2h2(P.w), tin[P.z * 8 + lane], acc);
    }
    if (e < end) {
        int2 E0 = e2[e];
        acc = __hfma2(b2h2(E0.y), tin[E0.x * 8 + lane], acc);
    }
    float2 a = __half22float2(acc);
    float dg = g_diag[n];
    float2 fs = __half22float2(tin[n * 8 + lane]);
    float rx = alpha * (dg * fs.x + a.x);
    float ry = alpha * (dg * fs.y + a.y);
    if (HASPREV) {
        float2 fp = __half22float2(tprev[n * 8 + lane]);
        rx -= fp.x; ry -= fp.y;
    }
    tout[n * 8 + lane] = __floats2half2_rn(rx, ry);
}

// F = 48: warp per node, lanes 0..23 own half2 column pairs (96B rows, unpadded).
template <bool HASPREV>
__global__ void k_prop48(const __half2* __restrict__ tin, const __half2* __restrict__ tprev,
                         __half2* __restrict__ tout, float alpha) {
    int n = (blockIdx.x * blockDim.x + threadIdx.x) >> 5;
    if (n >= NN) return;
    int lane = threadIdx.x & 31;
    bool act = lane < 24;
    int li = act ? lane : 0;
    int beg = g_rowptr[n], end = g_rowptr[n + 1];
    const int2* e2 = reinterpret_cast<const int2*>(g_edge4);
    __half2 acc = __float2half2_rn(0.0f);
    int e = beg;
    if ((e & 1) && e < end) {
        int2 E0 = e2[e];
        acc = __hfma2(b2h2(E0.y), tin[E0.x * 24 + li], acc);
        e++;
    }
    for (; e + 8 <= end; e += 8) {
        int4 P[4];
#pragma unroll
        for (int j = 0; j < 4; j++) P[j] = g_edge4[(e >> 1) + j];
        __half2 f[8];
#pragma unroll
        for (int j = 0; j < 4; j++) {
            f[2 * j]     = tin[P[j].x * 24 + li];
            f[2 * j + 1] = tin[P[j].z * 24 + li];
        }
#pragma unroll
        for (int j = 0; j < 4; j++) {
            acc = __hfma2(b2h2(P[j].y), f[2 * j], acc);
            acc = __hfma2(b2h2(P[j].w), f[2 * j + 1], acc);
        }
    }
    for (; e + 2 <= end; e += 2) {
        int4 P = g_edge4[e >> 1];
        acc = __hfma2(b2h2(P.y), tin[P.x * 24 + li], acc);
        acc = __hfma2(b2h2(P.w), tin[P.z * 24 + li], acc);
    }
    if (e < end) {
        int2 E0 = e2[e];
        acc = __hfma2(b2h2(E0.y), tin[E0.x * 24 + li], acc);
    }
    if (act) {
        float2 a = __half22float2(acc);
        float dg = g_diag[n];
        float2 fs = __half22float2(tin[n * 24 + lane]);
        float rx = alpha * (dg * fs.x + a.x);
        float ry = alpha * (dg * fs.y + a.y);
        if (HASPREV) {
            float2 fp = __half22float2(tprev[n * 24 + lane]);
            rx -= fp.x; ry -= fp.y;
        }
        tout[n * 24 + lane] = __floats2half2_rn(rx, ry);
    }
}

// ---------------- fused layer output: h = relu(b + sum_k T_k @ W[k]) ----------------
template <int FIN>
__global__ void k_mix(const __half2* __restrict__ T0, const __half2* __restrict__ T1,
                      const __half2* __restrict__ T2, const __half2* __restrict__ T3,
                      const __half2* __restrict__ T4,
                      const float* __restrict__ W, const float* __restrict__ b,
                      __half2* __restrict__ hout) {
    __shared__ __align__(16) float sW[5 * FIN * 48];
    const int tot = 5 * FIN * 48;
    for (int i = threadIdx.x; i < tot; i += blockDim.x) sW[i] = W[i];
    __syncthreads();
    int gid = blockIdx.x * blockDim.x + threadIdx.x;
    int n = gid / 12;
    int f = (gid % 12) * 4;
    if (n >= NN) return;
    const __half2* Ts[5] = {T0, T1, T2, T3, T4};
    float4 acc = *reinterpret_cast<const float4*>(&b[f]);
#pragma unroll
    for (int k = 0; k < 5; k++) {
        const __half2* T = Ts[k] + n * (FIN / 2);
        const float* wk = &sW[k * FIN * 48 + f];
#pragma unroll
        for (int i2 = 0; i2 < FIN / 2; i2++) {
            float2 v = __half22float2(T[i2]);
            float4 w0 = *reinterpret_cast<const float4*>(wk + (2 * i2) * 48);
            float4 w1 = *reinterpret_cast<const float4*>(wk + (2 * i2 + 1) * 48);
            acc.x += v.x * w0.x + v.y * w1.x;
            acc.y += v.x * w0.y + v.y * w1.y;
            acc.z += v.x * w0.z + v.y * w1.z;
            acc.w += v.x * w0.w + v.y * w1.w;
        }
    }
    acc.x = fmaxf(acc.x, 0.0f);
    acc.y = fmaxf(acc.y, 0.0f);
    acc.z = fmaxf(acc.z, 0.0f);
    acc.w = fmaxf(acc.w, 0.0f);
    hout[n * 24 + f / 2]     = __floats2half2_rn(acc.x, acc.y);
    hout[n * 24 + f / 2 + 1] = __floats2half2_rn(acc.z, acc.w);
}

// ---------------- global_add_pool + MLP head ----------------
__global__ void k_pool(const __half* __restrict__ h,
                       const float* __restrict__ fc1w, const float* __restrict__ fc1b,
                       const float* __restrict__ fc2w, const float* __restrict__ fc2b,
                       float* __restrict__ out) {
    const int g = blockIdx.x;
    const int tid = threadIdx.x;
    const int r = tid / 48, f = tid % 48;
    const int base = g * (NN / GG);
    float a = 0.0f;
    for (int n = base + r; n < base + (NN / GG); n += 10) a += __half2float(h[n * 48 + f]);
    __shared__ float red[480];
    __shared__ float pooled[48];
    __shared__ float o1[32];
    red[tid] = a;
    __syncthreads();
    if (tid < 48) {
        float s = 0.0f;
        for (int rr = 0; rr < 10; rr++) s += red[rr * 48 + tid];
        pooled[tid] = s;
    }
    __syncthreads();
    if (tid < 32) {
        float s = fc1b[tid];
        for (int i = 0; i < 48; i++) s += pooled[i] * fc1w[i * 32 + tid];
        o1[tid] = fmaxf(s, 0.0f);
    }
    __syncthreads();
    if (tid == 0) {
        float s = fc2b[0];
        for (int j = 0; j < 32; j++) s += o1[j] * fc2w[j];
        out[g] = s;
    }
}

// ---------------- host launcher ----------------
extern "C" void kernel_launch(void* const* d_in, const int* in_sizes, int n_in,
                              void* d_out, int out_size) {
    const float* x     = (const float*)d_in[0];
    const int*   ei    = (const int*)d_in[1];
    const int*   src   = ei;
    const int*   dst   = ei + EE;
    const int*   batch = (const int*)d_in[2];
    const float* lmax  = (const float*)d_in[3];
    const float* W[5]  = {(const float*)d_in[4], (const float*)d_in[6], (const float*)d_in[8],
                          (const float*)d_in[10], (const float*)d_in[12]};
    const float* B[5]  = {(const float*)d_in[5], (const float*)d_in[7], (const float*)d_in[9],
                          (const float*)d_in[11], (const float*)d_in[13]};
    const float* fc1w = (const float*)d_in[14];
    const float* fc1b = (const float*)d_in[15];
    const float* fc2w = (const float*)d_in[16];
    const float* fc2b = (const float*)d_in[17];
    float* out = (float*)d_out;

    void* p;
    cudaGetSymbolAddress(&p, g_degi); int* degi = (int*)p;
    cudaGetSymbolAddress(&p, g_cnt);  int* cnt = (int*)p;
    cudaGetSymbolAddress(&p, g_x16);  __half2* x16 = (__half2*)p;
    cudaGetSymbolAddress(&p, g_T1);   __half2* T1 = (__half2*)p;
    cudaGetSymbolAddress(&p, g_T2);   __half2* T2 = (__half2*)p;
    cudaGetSymbolAddress(&p, g_T3);   __half2* T3 = (__half2*)p;
    cudaGetSymbolAddress(&p, g_T4);   __half2* T4 = (__half2*)p;
    cudaGetSymbolAddress(&p, g_hA);   __half2* hA = (__half2*)p;
    cudaGetSymbolAddress(&p, g_hB);   __half2* hB = (__half2*)p;

    cudaMemsetAsync(degi, 0, NN * sizeof(int), 0);
    cudaMemsetAsync(cnt, 0, NN * sizeof(int), 0);
    k_degree<<<(EE + 255) / 256, 256>>>(src, dst);
    k_node<<<(NN + 255) / 256, 256>>>(batch, lmax);
    k_scan<<<1, 1024>>>();
    cudaMemsetAsync(cnt, 0, NN * sizeof(int), 0);
    k_fill<<<(EE + 255) / 256, 256>>>(src, dst, lmax);
    k_xcast<<<(NN * 8 + 255) / 256, 256>>>(x);

    const int PB = 256;
    const int pgrid48 = (NN * 32 + PB - 1) / PB;  // warp per node
    const int pgrid16 = (NN * 8 + PB - 1) / PB;   // 8 lanes per node
    const int mgrid = (NN * 12 + 255) / 256;

    // layer 1 (F_in = 16, T0 = x16)
    k_prop16<false><<<pgrid16, PB>>>(x16, nullptr, T1, 1.0f);
    k_prop16<true><<<pgrid16, PB>>>(T1, x16, T2, 2.0f);
    k_prop16<true><<<pgrid16, PB>>>(T2, T1, T3, 2.0f);
    k_prop16<true><<<pgrid16, PB>>>(T3, T2, T4, 2.0f);
    k_mix<16><<<mgrid, 256>>>(x16, T1, T2, T3, T4, W[0], B[0], hA);

    // layers 2..5 (F_in = 48), ping-pong hA <-> hB
    __half2* cur = hA;
    __half2* nxt = hB;
    for (int l = 1; l < 5; l++) {
        k_prop48<false><<<pgrid48, PB>>>(cur, nullptr, T1, 1.0f);
        k_prop48<true><<<pgrid48, PB>>>(T1, cur, T2, 2.0f);
        k_prop48<true><<<pgrid48, PB>>>(T2, T1, T3, 2.0f);
        k_prop48<true><<<pgrid48, PB>>>(T3, T2, T4, 2.0f);
        k_mix<48><<<mgrid, 256>>>(cur, T1, T2, T3, T4, W[l], B[l], nxt);
        __half2* t = cur; cur = nxt; nxt = t;
    }

    k_pool<<<GG, 480>>>((const __half*)cur, fc1w, fc1b, fc2w, fc2b, out);
}

// round 12
// speedup vs baseline: 1.2939x; 1.0379x over previous
#include <cuda_runtime.h>
#include <cuda_fp16.h>

#define NN 100000
#define EE 3200000
#define GG 100
#define HH 48

// ---------------- device scratch ----------------
__device__ int   g_degi[NN];          // out-degree (for dis)
__device__ int   g_cnt[NN];           // in-degree, then placement counter
__device__ int   g_dbin[256];         // degree histogram -> start offsets
__device__ int   g_order[NN];         // nodes sorted by descending in-degree
__device__ float g_dis[NN];
__device__ float g_diag[NN];
__device__ int   g_rowptr[NN + 1];
__device__ int2  g_edge[EE];          // {src, weight as half2 (broadcast) bits}, by dst
__device__ __half g_x16[NN * 16];
__device__ __half g_T1[NN * HH];
__device__ __half g_T2[NN * HH];
__device__ __half g_T3[NN * HH];
__device__ __half g_T4[NN * HH];
__device__ __half g_hA[NN * HH];
__device__ __half g_hB[NN * HH];

// ---------------- graph preprocessing ----------------
__global__ void k_degree(const int* __restrict__ src, const int* __restrict__ dst) {
    int e = blockIdx.x * blockDim.x + threadIdx.x;
    if (e >= EE) return;
    atomicAdd(&g_degi[src[e]], 1);
    atomicAdd(&g_cnt[dst[e]], 1);
}

// per-node terms + in-degree histogram
__global__ void k_node(const int* __restrict__ batch, const float* __restrict__ lmax) {
    int n = blockIdx.x * blockDim.x + threadIdx.x;
    if (n >= NN) return;
    float d = (float)g_degi[n];
    g_dis[n] = (d > 0.0f) ? rsqrtf(d) : 0.0f;
    g_diag[n] = 2.0f / lmax[batch[n]] - 1.0f;
    int b = g_cnt[n]; if (b > 255) b = 255;
    atomicAdd(&g_dbin[b], 1);
}

// single-block exclusive scan of g_cnt -> g_rowptr
__global__ void k_scan() {
    __shared__ int sums[1024];
    const int tid = threadIdx.x;
    const int CH = (NN + 1023) / 1024;
    int start = tid * CH;
    int end = start + CH; if (end > NN) end = NN; if (start > NN) start = NN;
    int s = 0;
    for (int i = start; i < end; i++) s += g_cnt[i];
    sums[tid] = s;
    __syncthreads();
    for (int off = 1; off < 1024; off <<= 1) {
        int v = (tid >= off) ? sums[tid - off] : 0;
        __syncthreads();
        sums[tid] += v;
        __syncthreads();
    }
    int run = sums[tid] - s;
    for (int i = start; i < end; i++) {
        g_rowptr[i] = run;
        run += g_cnt[i];
    }
    if (tid == 1023) g_rowptr[NN] = run;
}

// descending-degree bin start offsets (suffix sum); 256 bins, trivial single-thread
__global__ void k_binscan() {
    if (threadIdx.x == 0) {
        int run = 0;
        for (int b = 255; b >= 0; b--) {
            int c = g_dbin[b];
            g_dbin[b] = run;
            run += c;
        }
    }
}

// scatter nodes into degree-sorted order
__global__ void k_scatter() {
    int n = blockIdx.x * blockDim.x + threadIdx.x;
    if (n >= NN) return;
    int b = g_cnt[n]; if (b > 255) b = 255;
    int pos = atomicAdd(&g_dbin[b], 1);
    g_order[pos] = n;
}

__global__ void k_fill(const int* __restrict__ src, const int* __restrict__ dst,
                       const float* __restrict__ lmax) {
    int e = blockIdx.x * blockDim.x + threadIdx.x;
    if (e >= EE) return;
    int s = src[e], d = dst[e];
    int pos = g_rowptr[d] + atomicAdd(&g_cnt[d], 1);
    float w = -2.0f * g_dis[s] * g_dis[d] / lmax[s / (NN / GG)];
    __half2 w2 = __half2half2(__float2half_rn(w));
    g_edge[pos] = make_int2(s, *reinterpret_cast<const int*>(&w2));
}

__global__ void k_xcast(const float* __restrict__ x) {
    int i = blockIdx.x * blockDim.x + threadIdx.x;
    if (i >= NN * 8) return;
    float2 v = reinterpret_cast<const float2*>(x)[i];
    reinterpret_cast<__half2*>(g_x16)[i] = __floats2half2_rn(v.x, v.y);
}

// ---------------- Chebyshev propagation (fp16, HFMA2, degree-ordered schedule) -------
// F = 16: 8 lanes per node (degree-sorted), each lane owns one half2 column pair.
template <bool HASPREV>
__global__ void k_prop16(const __half2* __restrict__ tin, const __half2* __restrict__ tprev,
                         __half2* __restrict__ tout, float alpha) {
    int t = blockIdx.x * blockDim.x + threadIdx.x;
    int ni = t >> 3;
    if (ni >= NN) return;
    int n = g_order[ni];
    int lane = t & 7;
    int beg = g_rowptr[n], end = g_rowptr[n + 1];
    __half2 acc = __float2half2_rn(0.0f);
    int e = beg;
    for (; e + 8 <= end; e += 8) {
        int2 E[8];
#pragma unroll
        for (int j = 0; j < 8; j++) E[j] = g_edge[e + j];
        __half2 f[8];
#pragma unroll
        for (int j = 0; j < 8; j++) f[j] = tin[E[j].x * 8 + lane];
#pragma unroll
        for (int j = 0; j < 8; j++)
            acc = __hfma2(*reinterpret_cast<const __half2*>(&E[j].y), f[j], acc);
    }
    for (; e < end; e++) {
        int2 E0 = g_edge[e];
        __half2 f0 = tin[E0.x * 8 + lane];
        acc = __hfma2(*reinterpret_cast<const __half2*>(&E0.y), f0, acc);
    }
    float2 a = __half22float2(acc);
    float dg = g_diag[n];
    float2 fs = __half22float2(tin[n * 8 + lane]);
    float rx = alpha * (dg * fs.x + a.x);
    float ry = alpha * (dg * fs.y + a.y);
    if (HASPREV) {
        float2 fp = __half22float2(tprev[n * 8 + lane]);
        rx -= fp.x; ry -= fp.y;
    }
    tout[n * 8 + lane] = __floats2half2_rn(rx, ry);
}

// F = 48: warp per node (degree-sorted), lanes 0..23 own half2 column pairs.
template <bool HASPREV>
__global__ void k_prop48(const __half2* __restrict__ tin, const __half2* __restrict__ tprev,
                         __half2* __restrict__ tout, float alpha) {
    int ni = (blockIdx.x * blockDim.x + threadIdx.x) >> 5;
    if (ni >= NN) return;
    int n = g_order[ni];
    int lane = threadIdx.x & 31;
    bool act = lane < 24;
    int li = act ? lane : 0;
    int beg = g_rowptr[n], end = g_rowptr[n + 1];
    __half2 acc = __float2half2_rn(0.0f);
    int e = beg;
    for (; e + 8 <= end; e += 8) {
        int2 E[8];
#pragma unroll
        for (int j = 0; j < 8; j++) E[j] = g_edge[e + j];
        __half2 f[8];
#pragma unroll
        for (int j = 0; j < 8; j++) f[j] = tin[E[j].x * 24 + li];
#pragma unroll
        for (int j = 0; j < 8; j++)
            acc = __hfma2(*reinterpret_cast<const __half2*>(&E[j].y), f[j], acc);
    }
    for (; e < end; e++) {
        int2 E0 = g_edge[e];
        __half2 f0 = tin[E0.x * 24 + li];
        acc = __hfma2(*reinterpret_cast<const __half2*>(&E0.y), f0, acc);
    }
    if (act) {
        float2 a = __half22float2(acc);
        float dg = g_diag[n];
        float2 fs = __half22float2(tin[n * 24 + lane]);
        float rx = alpha * (dg * fs.x + a.x);
        float ry = alpha * (dg * fs.y + a.y);
        if (HASPREV) {
            float2 fp = __half22float2(tprev[n * 24 + lane]);
            rx -= fp.x; ry -= fp.y;
        }
        tout[n * 24 + lane] = __floats2half2_rn(rx, ry);
    }
}

// ---------------- fused layer output: h = relu(b + sum_k T_k @ W[k]) ----------------
template <int FIN>
__global__ void k_mix(const __half2* __restrict__ T0, const __half2* __restrict__ T1,
                      const __half2* __restrict__ T2, const __half2* __restrict__ T3,
                      const __half2* __restrict__ T4,
                      const float* __restrict__ W, const float* __restrict__ b,
                      __half2* __restrict__ hout) {
    __shared__ __align__(16) float sW[5 * FIN * 48];
    const int tot = 5 * FIN * 48;
    for (int i = threadIdx.x; i < tot; i += blockDim.x) sW[i] = W[i];
    __syncthreads();
    int gid = blockIdx.x * blockDim.x + threadIdx.x;
    int n = gid / 12;
    int f = (gid % 12) * 4;
    if (n >= NN) return;
    const __half2* Ts[5] = {T0, T1, T2, T3, T4};
    float4 acc = *reinterpret_cast<const float4*>(&b[f]);
#pragma unroll
    for (int k = 0; k < 5; k++) {
        const __half2* T = Ts[k] + n * (FIN / 2);
        const float* wk = &sW[k * FIN * 48 + f];
#pragma unroll
        for (int i2 = 0; i2 < FIN / 2; i2++) {
            float2 v = __half22float2(T[i2]);
            float4 w0 = *reinterpret_cast<const float4*>(wk + (2 * i2) * 48);
            float4 w1 = *reinterpret_cast<const float4*>(wk + (2 * i2 + 1) * 48);
            acc.x += v.x * w0.x + v.y * w1.x;
            acc.y += v.x * w0.y + v.y * w1.y;
            acc.z += v.x * w0.z + v.y * w1.z;
            acc.w += v.x * w0.w + v.y * w1.w;
        }
    }
    acc.x = fmaxf(acc.x, 0.0f);
    acc.y = fmaxf(acc.y, 0.0f);
    acc.z = fmaxf(acc.z, 0.0f);
    acc.w = fmaxf(acc.w, 0.0f);
    hout[n * 24 + f / 2]     = __floats2half2_rn(acc.x, acc.y);
    hout[n * 24 + f / 2 + 1] = __floats2half2_rn(acc.z, acc.w);
}

// ---------------- global_add_pool + MLP head ----------------
__global__ void k_pool(const __half* __restrict__ h,
                       const float* __restrict__ fc1w, const float* __restrict__ fc1b,
                       const float* __restrict__ fc2w, const float* __restrict__ fc2b,
                       float* __restrict__ out) {
    const int g = blockIdx.x;
    const int tid = threadIdx.x;
    const int r = tid / 48, f = tid % 48;
    const int base = g * (NN / GG);
    float a = 0.0f;
    for (int n = base + r; n < base + (NN / GG); n += 10) a += __half2float(h[n * 48 + f]);
    __shared__ float red[480];
    __shared__ float pooled[48];
    __shared__ float o1[32];
    red[tid] = a;
    __syncthreads();
    if (tid < 48) {
        float s = 0.0f;
        for (int rr = 0; rr < 10; rr++) s += red[rr * 48 + tid];
        pooled[tid] = s;
    }
    __syncthreads();
    if (tid < 32) {
        float s = fc1b[tid];
        for (int i = 0; i < 48; i++) s += pooled[i] * fc1w[i * 32 + tid];
        o1[tid] = fmaxf(s, 0.0f);
    }
    __syncthreads();
    if (tid == 0) {
        float s = fc2b[0];
        for (int j = 0; j < 32; j++) s += o1[j] * fc2w[j];
        out[g] = s;
    }
}

// ---------------- host launcher ----------------
extern "C" void kernel_launch(void* const* d_in, const int* in_sizes, int n_in,
                              void* d_out, int out_size) {
    const float* x     = (const float*)d_in[0];
    const int*   ei    = (const int*)d_in[1];
    const int*   src   = ei;
    const int*   dst   = ei + EE;
    const int*   batch = (const int*)d_in[2];
    const float* lmax  = (const float*)d_in[3];
    const float* W[5]  = {(const float*)d_in[4], (const float*)d_in[6], (const float*)d_in[8],
                          (const float*)d_in[10], (const float*)d_in[12]};
    const float* B[5]  = {(const float*)d_in[5], (const float*)d_in[7], (const float*)d_in[9],
                          (const float*)d_in[11], (const float*)d_in[13]};
    const float* fc1w = (const float*)d_in[14];
    const float* fc1b = (const float*)d_in[15];
    const float* fc2w = (const float*)d_in[16];
    const float* fc2b = (const float*)d_in[17];
    float* out = (float*)d_out;

    void* p;
    cudaGetSymbolAddress(&p, g_degi); int* degi = (int*)p;
    cudaGetSymbolAddress(&p, g_cnt);  int* cnt = (int*)p;
    cudaGetSymbolAddress(&p, g_dbin); int* dbin = (int*)p;
    cudaGetSymbolAddress(&p, g_x16);  __half2* x16 = (__half2*)p;
    cudaGetSymbolAddress(&p, g_T1);   __half2* T1 = (__half2*)p;
    cudaGetSymbolAddress(&p, g_T2);   __half2* T2 = (__half2*)p;
    cudaGetSymbolAddress(&p, g_T3);   __half2* T3 = (__half2*)p;
    cudaGetSymbolAddress(&p, g_T4);   __half2* T4 = (__half2*)p;
    cudaGetSymbolAddress(&p, g_hA);   __half2* hA = (__half2*)p;
    cudaGetSymbolAddress(&p, g_hB);   __half2* hB = (__half2*)p;

    cudaMemsetAsync(degi, 0, NN * sizeof(int), 0);
    cudaMemsetAsync(cnt, 0, NN * sizeof(int), 0);
    cudaMemsetAsync(dbin, 0, 256 * sizeof(int), 0);
    k_degree<<<(EE + 255) / 256, 256>>>(src, dst);
    k_node<<<(NN + 255) / 256, 256>>>(batch, lmax);
    k_scan<<<1, 1024>>>();
    k_binscan<<<1, 32>>>();
    k_scatter<<<(NN + 255) / 256, 256>>>();
    cudaMemsetAsync(cnt, 0, NN * sizeof(int), 0);
    k_fill<<<(EE + 255) / 256, 256>>>(src, dst, lmax);
    k_xcast<<<(NN * 8 + 255) / 256, 256>>>(x);

    const int PB = 128;                            // smaller retirement granularity
    const int pgrid48 = (NN * 32 + PB - 1) / PB;   // warp per node
    const int pgrid16 = (NN * 8 + PB - 1) / PB;    // 8 lanes per node
    const int mgrid = (NN * 12 + 255) / 256;

    // layer 1 (F_in = 16, T0 = x16)
    k_prop16<false><<<pgrid16, PB>>>(x16, nullptr, T1, 1.0f);
    k_prop16<true><<<pgrid16, PB>>>(T1, x16, T2, 2.0f);
    k_prop16<true><<<pgrid16, PB>>>(T2, T1, T3, 2.0f);
    k_prop16<true><<<pgrid16, PB>>>(T3, T2, T4, 2.0f);
    k_mix<16><<<mgrid, 256>>>(x16, T1, T2, T3, T4, W[0], B[0], hA);

    // layers 2..5 (F_in = 48), ping-pong hA <-> hB
    __half2* cur = hA;
    __half2* nxt = hB;
    for (int l = 1; l < 5; l++) {
        k_prop48<false><<<pgrid48, PB>>>(cur, nullptr, T1, 1.0f);
        k_prop48<true><<<pgrid48, PB>>>(T1, cur, T2, 2.0f);
        k_prop48<true><<<pgrid48, PB>>>(T2, T1, T3, 2.0f);
        k_prop48<true><<<pgrid48, PB>>>(T3, T2, T4, 2.0f);
        k_mix<48><<<mgrid, 256>>>(cur, T1, T2, T3, T4, W[l], B[l], nxt);
        __half2* t = cur; cur = nxt; nxt = t;
    }

    k_pool<<<GG, 480>>>((const __half*)cur, fc1w, fc1b, fc2w, fc2b, out);
}